// round 15
// baseline (speedup 1.0000x reference)
#include <cuda_runtime.h>
#include <cuda_bf16.h>
#include <cstdint>

#define N_IN  5023
#define N_OUT 5023
#define HD    256
#define MP    5120
#define NV    192
#define WSPLIT 10
#define LDA   40            // bf16 elems per smem row (32 + 8 skew) = 80B

// -------- scratch --------
__device__ __nv_bfloat16 g_Qb[(size_t)MP * HD];  // [o][h] bf16
__device__ __nv_bfloat16 g_Kb[(size_t)MP * HD];  // [i][h] bf16
__device__ float g_l1p[40 * MP];
__device__ float g_V2[(size_t)MP * NV];
__device__ float g_Wp[WSPLIT * HD * NV];
__device__ float g_W[HD * NV];

// -------- helpers --------
__device__ __forceinline__ uint32_t s2u(const void* p) {
    return (uint32_t)__cvta_generic_to_shared(p);
}
__device__ __forceinline__ void ldsm4(uint32_t* r, uint32_t a) {
    asm volatile("ldmatrix.sync.aligned.m8n8.x4.shared.b16 {%0,%1,%2,%3}, [%4];"
                 : "=r"(r[0]), "=r"(r[1]), "=r"(r[2]), "=r"(r[3]) : "r"(a));
}
__device__ __forceinline__ void mma16816(float* d, const uint32_t* a, const uint32_t* b) {
    asm volatile("mma.sync.aligned.m16n8k16.row.col.f32.bf16.bf16.f32 "
                 "{%0,%1,%2,%3},{%4,%5,%6,%7},{%8,%9},{%0,%1,%2,%3};"
                 : "+f"(d[0]), "+f"(d[1]), "+f"(d[2]), "+f"(d[3])
                 : "r"(a[0]), "r"(a[1]), "r"(a[2]), "r"(a[3]), "r"(b[0]), "r"(b[1]));
}
__device__ __forceinline__ void cpasync16(uint32_t dst, const void* src) {
    asm volatile("cp.async.cg.shared.global [%0], [%1], 16;" :: "r"(dst), "l"(src));
}

// -------- prep --------
__global__ void qconv(const float* __restrict__ qw) {
    __shared__ float t[32][33];
    const int o0 = blockIdx.x * 32, h0 = blockIdx.y * 32;
    const int tx = threadIdx.x & 31, ty = threadIdx.x >> 5;   // 32 x 8
    #pragma unroll
    for (int j = 0; j < 4; j++) {
        int h = h0 + ty + j * 8, o = o0 + tx;
        t[ty + j * 8][tx] = (o < N_OUT) ? qw[(size_t)h * N_OUT + o] : 0.f;
    }
    __syncthreads();
    #pragma unroll
    for (int j = 0; j < 4; j++) {
        int o = o0 + ty + j * 8, h = h0 + tx;
        g_Qb[(size_t)o * HD + h] = __float2bfloat16(t[tx][ty + j * 8]);
    }
}
__global__ void kconv(const float* __restrict__ kw) {
    int idx = blockIdx.x * 256 + threadIdx.x;
    if (idx >= MP * HD) return;
    int i = idx / HD;
    g_Kb[idx] = __float2bfloat16((i < N_IN) ? kw[idx] : 0.f);
}

// -------- fused GEMM1 + |.| column reduction --------
// BM=BN=128, BK=32 double-buffered cp.async; 256 thr, 2 CTAs/SM.
// warps 2(M)x4(N), warp tile 64x32.
__global__ __launch_bounds__(256, 2) void gemm1_l1() {
    __shared__ __nv_bfloat16 As[2][128 * LDA];
    __shared__ __nv_bfloat16 Bs[2][128 * LDA];
    __shared__ float Cs[256];
    const int tid = threadIdx.x, lane = tid & 31, wid = tid >> 5;
    const int wm = (wid >> 2) * 64, wn = (wid & 3) * 32;
    const size_t obase = (size_t)blockIdx.y * 128, ibase = (size_t)blockIdx.x * 128;

    const int ld_r = tid >> 1, ld_c0 = (tid & 1) * 16;   // 2 chunks of 8 per thread per array

#define LOAD_STAGE(S, B)                                                            \
    {                                                                               \
        const int k0 = (S) * 32;                                                    \
        _Pragma("unroll")                                                           \
        for (int j = 0; j < 2; j++) {                                               \
            int c8 = ld_c0 + j * 8;                                                 \
            cpasync16(s2u(&As[(B)][ld_r * LDA + c8]), &g_Qb[(obase + ld_r) * HD + k0 + c8]); \
            cpasync16(s2u(&Bs[(B)][ld_r * LDA + c8]), &g_Kb[(ibase + ld_r) * HD + k0 + c8]); \
        }                                                                           \
        asm volatile("cp.async.commit_group;" ::: "memory");                        \
    }

    LOAD_STAGE(0, 0);

    float acc[4][4][4] = {};
    const int a_row = lane & 15;
    const int a_col = (lane >> 4) * 8;
    const int b_row = ((lane >> 4) & 1) * 8 + (lane & 7);
    const int b_col = ((lane >> 3) & 1) * 8;

    #pragma unroll
    for (int s = 0; s < 8; s++) {
        asm volatile("cp.async.wait_group 0;" ::: "memory");
        __syncthreads();
        if (s < 7) LOAD_STAGE(s + 1, (s + 1) & 1);
        const uint32_t aB = s2u(&As[s & 1][0]);
        const uint32_t bB = s2u(&Bs[s & 1][0]);
        #pragma unroll
        for (int ks = 0; ks < 32; ks += 16) {
            uint32_t fa[4][4], fb[4][2];
            #pragma unroll
            for (int mt = 0; mt < 4; mt++)
                ldsm4(fa[mt], aB + (uint32_t)((wm + mt * 16 + a_row) * LDA + ks + a_col) * 2);
            #pragma unroll
            for (int nt2 = 0; nt2 < 2; nt2++) {
                uint32_t t[4];
                ldsm4(t, bB + (uint32_t)((wn + nt2 * 16 + b_row) * LDA + ks + b_col) * 2);
                fb[nt2 * 2][0] = t[0]; fb[nt2 * 2][1] = t[1];
                fb[nt2 * 2 + 1][0] = t[2]; fb[nt2 * 2 + 1][1] = t[3];
            }
            #pragma unroll
            for (int mt = 0; mt < 4; mt++)
                #pragma unroll
                for (int nt = 0; nt < 4; nt++)
                    mma16816(acc[mt][nt], fa[mt], fb[nt]);
        }
        __syncthreads();
    }
#undef LOAD_STAGE

    // column |.| sums
    const int t4 = lane & 3;
    float cs[4][2];
    #pragma unroll
    for (int nt = 0; nt < 4; nt++) {
        float s0 = 0.f, s1 = 0.f;
        #pragma unroll
        for (int mt = 0; mt < 4; mt++) {
            s0 += fabsf(acc[mt][nt][0]) + fabsf(acc[mt][nt][2]);
            s1 += fabsf(acc[mt][nt][1]) + fabsf(acc[mt][nt][3]);
        }
        cs[nt][0] = s0; cs[nt][1] = s1;
    }
    #pragma unroll
    for (int m = 4; m <= 16; m <<= 1)
        #pragma unroll
        for (int nt = 0; nt < 4; nt++) {
            cs[nt][0] += __shfl_xor_sync(0xffffffff, cs[nt][0], m);
            cs[nt][1] += __shfl_xor_sync(0xffffffff, cs[nt][1], m);
        }
    if (lane < 4) {
        #pragma unroll
        for (int nt = 0; nt < 4; nt++) {
            Cs[(wm >> 6) * 128 + wn + nt * 8 + 2 * t4 + 0] = cs[nt][0];
            Cs[(wm >> 6) * 128 + wn + nt * 8 + 2 * t4 + 1] = cs[nt][1];
        }
    }
    __syncthreads();
    if (tid < 128)
        g_l1p[blockIdx.y * MP + ibase + tid] = Cs[tid] + Cs[128 + tid];
}

// -------- fused l1-reduce + V build --------
// block: 32 i's. Phase1: rl1 for the slab; Phase2: stage x; Phase3: V2 slab.
__global__ __launch_bounds__(256) void vmat_l1(const float* __restrict__ x,
                                               const float* __restrict__ vw) {
    __shared__ float red[8][32];
    __shared__ float rl1s[32];
    __shared__ float xs[64][97];   // [b][i_l*3+d]
    const int tid = threadIdx.x;
    const int i0 = blockIdx.x * 32;

    // phase 1: rl1
    {
        const int part = tid >> 5, il = tid & 31;
        float s = 0.f;
        #pragma unroll
        for (int y = 0; y < 5; y++) s += g_l1p[(part + y * 8) * MP + i0 + il];
        red[part][il] = s;
    }
    __syncthreads();
    if (tid < 32) {
        float s = 0.f;
        #pragma unroll
        for (int p = 0; p < 8; p++) s += red[p][tid];
        rl1s[tid] = 0.0625f / fmaxf(s * 0.0625f, 1e-12f);
    }

    float vr[9];
    #pragma unroll
    for (int j = 0; j < 9; j++) vr[j] = vw[j];

    // phase 2: stage x slab [64 b][32 i][3] (guarded scalar loads)
    #pragma unroll
    for (int t = 0; t < 24; t++) {
        int flat = tid + t * 256;           // < 6144
        int b = flat / 96, c = flat % 96;
        int i = i0 + c / 3;
        xs[b][c] = (i < N_IN) ? x[((size_t)b * N_IN + i0) * 3 + c] : 0.f;
    }
    __syncthreads();

    // phase 3: V2[(i0+il)*192 + n]
    #pragma unroll
    for (int t = 0; t < 24; t++) {
        int q = tid + t * 256;              // < 6144
        int il = q / 192, n = q % 192;
        int b = n / 3, d = n % 3;
        float val = 0.f;
        if (i0 + il < N_IN) {
            val = (xs[b][il * 3 + 0] * vr[d * 3 + 0] +
                   xs[b][il * 3 + 1] * vr[d * 3 + 1] +
                   xs[b][il * 3 + 2] * vr[d * 3 + 2]) * rl1s[il];
        }
        g_V2[(size_t)(i0) * NV + q] = val;
    }
}

// -------- W partials --------
__global__ __launch_bounds__(256) void wgemm(const float* __restrict__ kw) {
    __shared__ float Ks[128][68];
    __shared__ float Vs[128][52];
    const int tid = threadIdx.x;
    const int ht = (blockIdx.x & 3) * 64;
    const int ntile = (blockIdx.x >> 2) * 48;
    const int i00 = blockIdx.y * 512;

    const int th = (tid & 15) * 4, tn = (tid >> 4) * 3;
    float acc[4][3] = {};

    for (int ch = 0; ch < 4; ch++) {
        const int i0 = i00 + ch * 128;
        #pragma unroll
        for (int s = 0; s < 8; s++) {
            int v = tid + s * 256;
            int r = v >> 4, c = (v & 15) * 4;
            int gi = i0 + r;
            float4 val = make_float4(0.f, 0.f, 0.f, 0.f);
            if (gi < N_IN) val = *(const float4*)&kw[(size_t)gi * HD + ht + c];
            *(float4*)&Ks[r][c] = val;
        }
        #pragma unroll
        for (int s = 0; s < 6; s++) {
            int v = tid + s * 256;
            int r = v / 12, c = (v % 12) * 4;
            *(float4*)&Vs[r][c] = *(const float4*)&g_V2[(size_t)(i0 + r) * NV + ntile + c];
        }
        __syncthreads();
        for (int kk = 0; kk < 128; kk++) {
            float ra[4], rb[3];
            #pragma unroll
            for (int u = 0; u < 4; u++) ra[u] = Ks[kk][th + u];
            #pragma unroll
            for (int u = 0; u < 3; u++) rb[u] = Vs[kk][tn + u];
            #pragma unroll
            for (int a = 0; a < 4; a++)
                #pragma unroll
                for (int b = 0; b < 3; b++)
                    acc[a][b] += ra[a] * rb[b];
        }
        __syncthreads();
    }
    float* dst = &g_Wp[(size_t)blockIdx.y * HD * NV];
    #pragma unroll
    for (int a = 0; a < 4; a++)
        #pragma unroll
        for (int b = 0; b < 3; b++)
            dst[(ht + th + a) * NV + ntile + tn + b] = acc[a][b];
}

__global__ void wreduce() {
    int idx = blockIdx.x * 256 + threadIdx.x;
    if (idx >= HD * NV) return;
    float s = 0.f;
    #pragma unroll
    for (int y = 0; y < WSPLIT; y++) s += g_Wp[(size_t)y * HD * NV + idx];
    g_W[idx] = s;
}

// -------- final: out[o,n] = sum_h qw[h][o] * W[h][n] --------
__global__ __launch_bounds__(256) void gemm3(const float* __restrict__ qw,
                                             float* __restrict__ out) {
    __shared__ float Qs[16][128];
    __shared__ float Ws[16][52];
    const int tid = threadIdx.x;
    const int ob = blockIdx.y * 128;
    const int nb = blockIdx.x * 48;

    const int to = (tid & 31) * 4, tn = (tid >> 5) * 6;
    float acc[4][6] = {};

    for (int h0 = 0; h0 < HD; h0 += 16) {
        #pragma unroll
        for (int s = 0; s < 8; s++) {
            int v = tid + s * 256;
            int r = v >> 7, c = v & 127;
            int go = ob + c;
            Qs[r][c] = (go < N_OUT) ? qw[(size_t)(h0 + r) * N_OUT + go] : 0.f;
        }
        for (int v = tid; v < 768; v += 256) {
            int r = v / 48, c = v % 48;
            Ws[r][c] = g_W[(h0 + r) * NV + nb + c];
        }
        __syncthreads();
        #pragma unroll
        for (int kk = 0; kk < 16; kk++) {
            float ra[4], rb[6];
            #pragma unroll
            for (int u = 0; u < 4; u++) ra[u] = Qs[kk][to + u];
            #pragma unroll
            for (int u = 0; u < 6; u++) rb[u] = Ws[kk][tn + u];
            #pragma unroll
            for (int a = 0; a < 4; a++)
                #pragma unroll
                for (int b = 0; b < 6; b++)
                    acc[a][b] += ra[a] * rb[b];
        }
        __syncthreads();
    }

    #pragma unroll
    for (int a = 0; a < 4; a++) {
        int o = ob + to + a;
        if (o >= N_OUT) continue;
        #pragma unroll
        for (int b = 0; b < 6; b++) {
            int n = nb + tn + b;
            out[((size_t)(n / 3) * N_OUT + o) * 3 + (n % 3)] = acc[a][b];
        }
    }
}

// -------- launch --------
extern "C" void kernel_launch(void* const* d_in, const int* in_sizes, int n_in,
                              void* d_out, int out_size) {
    const float* x  = (const float*)d_in[0];
    const float* kw = (const float*)d_in[1];
    const float* qw = (const float*)d_in[2];
    const float* vw = (const float*)d_in[3];
    float* out = (float*)d_out;
    (void)in_sizes; (void)n_in; (void)out_size;

    qconv<<<dim3(160, 8), 256>>>(qw);
    kconv<<<(MP * HD + 255) / 256, 256>>>(kw);

    gemm1_l1<<<dim3(40, 40), 256>>>();

    vmat_l1<<<MP / 32, 256>>>(x, vw);
    wgemm<<<dim3(16, WSPLIT), 256>>>(kw);
    wreduce<<<(HD * NV + 255) / 256, 256>>>();

    gemm3<<<dim3(4, 40), 256>>>(qw, out);
}